// round 1
// baseline (speedup 1.0000x reference)
#include <cuda_runtime.h>
#include <math.h>

#define MAXN 20000
#define MAXE 320000

// ---------------- scratch (device globals; no runtime allocation) ----------
__device__ float g_pre[MAXN * 256];   // pre_x: [s(64) | v(64x3)]
__device__ float g_tmp[MAXN * 256];   // gated features before Wn e3_linear
__device__ float g_xg [MAXN * 256];   // xg (gather source for edges)
__device__ float g_acc[MAXN * 256];   // self_x + scatter accumulator
__device__ float g_h1a[MAXE * 32];
__device__ float g_h1l[MAXE * 32];
__device__ float g_WfT[320 * 32];     // Wf2^T * (1/sqrt(32))
__device__ float g_WlT[320 * 32];     // Wl2^T * (1/sqrt(32))
__device__ float g_Wl1s[64 * 32];     // (Wl1[u]+Wl1[u+64]) / sqrt(192)
__device__ float g_Wl1i[64 * 32];     // Wl1[u+128] / sqrt(192)

__device__ __forceinline__ float sspf(float x) {
    float sp = (x > 15.f) ? x : log1pf(expf(x));
    return sp - 0.69314718055994531f;
}
__device__ __forceinline__ float siluf(float x) {
    return x / (1.f + expf(-x));
}

// ---------------- weight prep --------------------------------------------
__global__ void prep_kernel(const float* __restrict__ Wf2,
                            const float* __restrict__ Wl2,
                            const float* __restrict__ Wl1) {
    int i = blockIdx.x * 256 + threadIdx.x;
    const float is32 = 0.17677669529663687f;   // 1/sqrt(32)
    if (i < 320 * 32) {
        int c = i >> 5, k = i & 31;
        g_WfT[i] = Wf2[k * 320 + c] * is32;
        g_WlT[i] = Wl2[k * 320 + c] * is32;
    }
    if (i < 64 * 32) {
        const float r192 = 0.07216878364870323f;  // 1/sqrt(192)
        g_Wl1s[i] = (Wl1[i] + Wl1[64 * 32 + i]) * r192;
        g_Wl1i[i] = Wl1[128 * 32 + i] * r192;
    }
}

// ---------------- generic e3_linear (s: 64->64 + bias, v: 64x3 -> 64x3) ---
__global__ void e3_kernel(const float* __restrict__ in,
                          const float* __restrict__ W0,
                          const float* __restrict__ b0,
                          const float* __restrict__ W1,
                          float* __restrict__ out,
                          float* __restrict__ out2, int nN) {
    __shared__ float W0s[64 * 64];
    __shared__ float W1s[64 * 64];
    __shared__ float b0s[64];
    __shared__ float ins[4][256];
    int tid = threadIdx.x;
    for (int i = tid; i < 4096; i += 256) { W0s[i] = W0[i]; W1s[i] = W1[i]; }
    if (tid < 64) b0s[tid] = b0[tid];
    int n0 = blockIdx.x * 4;
    for (int i = tid; i < 1024; i += 256) {
        int nl = i >> 8, f = i & 255;
        int n = n0 + nl;
        ins[nl][f] = (n < nN) ? in[n * 256 + f] : 0.f;
    }
    __syncthreads();
    int nl = tid >> 6, v = tid & 63;
    int n = n0 + nl;
    if (n < nN) {
        float accs = 0.f, a0 = 0.f, a1 = 0.f, a2 = 0.f;
        const float* row = ins[nl];
        #pragma unroll 16
        for (int u = 0; u < 64; u++) {
            float w0 = W0s[u * 64 + v];
            float w1 = W1s[u * 64 + v];
            accs += row[u] * w0;
            a0 += row[64 + u * 3 + 0] * w1;
            a1 += row[64 + u * 3 + 1] * w1;
            a2 += row[64 + u * 3 + 2] * w1;
        }
        float os = accs * 0.125f + b0s[v];
        float o0 = a0 * 0.125f, o1 = a1 * 0.125f, o2 = a2 * 0.125f;
        float* po = out + n * 256;
        po[v] = os;
        po[64 + v * 3 + 0] = o0;
        po[64 + v * 3 + 1] = o1;
        po[64 + v * 3 + 2] = o2;
        if (out2) {
            float* p2 = out2 + n * 256;
            p2[v] = os;
            p2[64 + v * 3 + 0] = o0;
            p2[64 + v * 3 + 1] = o1;
            p2[64 + v * 3 + 2] = o2;
        }
    }
}

// ---------------- gate MLP: g = silu(f0@Wg1+bg1)@Wg2+bg2; gated features --
__global__ void gate_kernel(const float* __restrict__ x,
                            const float* __restrict__ Wg1,
                            const float* __restrict__ bg1,
                            const float* __restrict__ Wg2,
                            const float* __restrict__ bg2,
                            float* __restrict__ outb, int nN) {
    extern __shared__ float sm[];
    float* W1s = sm;            // 16384
    float* W2s = sm + 16384;    // 16384
    float* f0s = sm + 32768;    // 1024
    float* hs  = sm + 33792;    // 1024
    int tid = threadIdx.x;
    for (int i = tid; i < 16384; i += 256) { W1s[i] = Wg1[i]; W2s[i] = Wg2[i]; }
    int n0 = blockIdx.x * 8;
    for (int i = tid; i < 1024; i += 256) {
        int nl = i >> 7, j = i & 127;
        int n = n0 + nl;
        float val = 0.f;
        if (n < nN) {
            const float* xr = x + n * 256;
            if (j < 64) val = xr[j];
            else {
                int u = j - 64;
                float v0 = xr[64 + u * 3], v1 = xr[64 + u * 3 + 1], v2 = xr[64 + u * 3 + 2];
                val = sqrtf(v0 * v0 + v1 * v1 + v2 * v2 + 1e-12f);
            }
        }
        f0s[i] = val;
    }
    __syncthreads();
    int j = tid & 127, half = tid >> 7;
    {
        float a0 = 0.f, a1 = 0.f, a2 = 0.f, a3 = 0.f;
        for (int k = 0; k < 128; k++) {
            float w = W1s[k * 128 + j];
            const float* f = f0s + half * 512 + k;
            a0 += f[0] * w; a1 += f[128] * w; a2 += f[256] * w; a3 += f[384] * w;
        }
        float b = bg1[j];
        hs[half * 512 + j]       = siluf(a0 + b);
        hs[half * 512 + 128 + j] = siluf(a1 + b);
        hs[half * 512 + 256 + j] = siluf(a2 + b);
        hs[half * 512 + 384 + j] = siluf(a3 + b);
    }
    __syncthreads();
    float a0 = 0.f, a1 = 0.f, a2 = 0.f, a3 = 0.f;
    for (int k = 0; k < 128; k++) {
        float w = W2s[k * 128 + j];
        const float* h = hs + half * 512 + k;
        a0 += h[0] * w; a1 += h[128] * w; a2 += h[256] * w; a3 += h[384] * w;
    }
    float b = bg2[j];
    float gg[4] = {a0 + b, a1 + b, a2 + b, a3 + b};
    #pragma unroll
    for (int nn = 0; nn < 4; nn++) {
        int n = n0 + half * 4 + nn;
        if (n >= nN) continue;
        float* o = outb + n * 256;
        if (j < 64) o[j] = gg[nn];
        else {
            int u = j - 64;
            const float* xr = x + n * 256 + 64 + u * 3;
            o[64 + u * 3 + 0] = xr[0] * gg[nn];
            o[64 + u * 3 + 1] = xr[1] * gg[nn];
            o[64 + u * 3 + 2] = xr[2] * gg[nn];
        }
    }
}

// ---------------- h1a = ssp(edge_attr @ Wf1 / 8) ---------------------------
__global__ void h1a_kernel(const float* __restrict__ attr,
                           const float* __restrict__ Wf1,
                           float* __restrict__ h1a, int nE) {
    __shared__ float attrs[64 * 64];
    __shared__ float Wf1s[64 * 32];
    int tid = threadIdx.x;
    int e0 = blockIdx.x * 64;
    for (int i = tid; i < 2048; i += 256) Wf1s[i] = Wf1[i];
    for (int i = tid; i < 4096; i += 256) {
        int e = e0 + (i >> 6);
        attrs[i] = (e < nE) ? attr[e * 64 + (i & 63)] : 0.f;
    }
    __syncthreads();
    int k = tid & 31, g = tid >> 5;   // 8 groups x 8 edges
    float acc[8] = {0.f, 0.f, 0.f, 0.f, 0.f, 0.f, 0.f, 0.f};
    for (int u = 0; u < 64; u++) {
        float w = Wf1s[u * 32 + k];
        #pragma unroll
        for (int ee = 0; ee < 8; ee++)
            acc[ee] += attrs[(g * 8 + ee) * 64 + u] * w;
    }
    #pragma unroll
    for (int ee = 0; ee < 8; ee++) {
        int e = e0 + g * 8 + ee;
        if (e < nE) h1a[e * 32 + k] = sspf(acc[ee] * 0.125f);
    }
}

// ---------------- h1l = ssp(s0 @ Wl1 / sqrt(192)) --------------------------
__global__ void h1l_kernel(const int* __restrict__ ei,
                           const float* __restrict__ pre,
                           float* __restrict__ h1l, int nE, int Etot) {
    __shared__ float ps_s[32 * 64];
    __shared__ float ip_s[32 * 64];
    __shared__ float Ws[64 * 32];
    __shared__ float Wi[64 * 32];
    __shared__ int dsts[32], srcs[32];
    int tid = threadIdx.x;
    int e0 = blockIdx.x * 32;
    for (int i = tid; i < 2048; i += 256) { Ws[i] = g_Wl1s[i]; Wi[i] = g_Wl1i[i]; }
    if (tid < 32) {
        int e = e0 + tid;
        dsts[tid] = (e < nE) ? ei[e] : 0;
        srcs[tid] = (e < nE) ? ei[Etot + e] : 0;
    }
    __syncthreads();
    for (int i = tid; i < 2048; i += 256) {
        int el = i >> 6, u = i & 63;
        int e = e0 + el;
        if (e < nE) {
            int d = dsts[el], s = srcs[el];
            ps_s[i] = pre[d * 256 + u];
            const float* pd = pre + d * 256 + 64 + u * 3;
            const float* pv = pre + s * 256 + 64 + u * 3;
            ip_s[i] = (pd[0] * pv[0] + pd[1] * pv[1] + pd[2] * pv[2]) * (1.f / 3.f);
        } else { ps_s[i] = 0.f; ip_s[i] = 0.f; }
    }
    __syncthreads();
    int k = tid & 31, g = tid >> 5;   // 8 groups x 4 edges
    float acc[4] = {0.f, 0.f, 0.f, 0.f};
    for (int u = 0; u < 64; u++) {
        float ws = Ws[u * 32 + k];
        float wi = Wi[u * 32 + k];
        #pragma unroll
        for (int ee = 0; ee < 4; ee++) {
            int el = g * 4 + ee;
            acc[ee] += ps_s[el * 64 + u] * ws + ip_s[el * 64 + u] * wi;
        }
    }
    #pragma unroll
    for (int ee = 0; ee < 4; ee++) {
        int e = e0 + g * 4 + ee;
        if (e < nE) h1l[e * 32 + k] = sspf(acc[ee]);
    }
}

// ---------------- fused edge kernel: w = (h1a@Wf2)*(h1l@Wl2); TP; scatter --
#define TE 64
__global__ void edge_kernel(const int* __restrict__ ei,
                            const float* __restrict__ sh,
                            const float* __restrict__ h1a,
                            const float* __restrict__ h1l,
                            const float* __restrict__ xg,
                            float* __restrict__ acc, int nE, int Etot) {
    extern __shared__ float sm[];
    float* hA  = sm;                     // 32 * 68
    float* hB  = sm + 32 * 68;           // 32 * 68
    float* ws  = sm + 2 * 32 * 68;       // 64 * 320
    float* shs = ws + 64 * 320;          // 64 * 4
    int*   idxs = (int*)(shs + 256);     // src[64] | dst[64]
    int tid = threadIdx.x;
    int e0 = blockIdx.x * TE;
    if (tid < 64) {
        int e = e0 + tid;
        bool v = (e < nE);
        idxs[tid]      = v ? ei[Etot + e] : 0;   // src
        idxs[64 + tid] = v ? ei[e] : -1;         // dst; -1 => skip
        float4 s4 = v ? *(const float4*)&sh[e * 4] : make_float4(0.f, 0.f, 0.f, 0.f);
        ((float4*)shs)[tid] = s4;
    }
    for (int i = tid; i < 2048; i += 320) {
        int el = i >> 5, k = i & 31;
        int e = e0 + el;
        float a = 0.f, b = 0.f;
        if (e < nE) { a = h1a[e * 32 + k]; b = h1l[e * 32 + k]; }
        hA[k * 68 + el] = a;
        hB[k * 68 + el] = b;
    }
    __syncthreads();
    // phase 1: per-column GEMM with weight columns in registers
    {
        int c = tid;  // 0..319
        float wf[32], wl[32];
        #pragma unroll
        for (int q = 0; q < 8; q++) {
            float4 f = ((const float4*)(g_WfT + c * 32))[q];
            wf[q * 4 + 0] = f.x; wf[q * 4 + 1] = f.y; wf[q * 4 + 2] = f.z; wf[q * 4 + 3] = f.w;
            float4 l = ((const float4*)(g_WlT + c * 32))[q];
            wl[q * 4 + 0] = l.x; wl[q * 4 + 1] = l.y; wl[q * 4 + 2] = l.z; wl[q * 4 + 3] = l.w;
        }
        for (int eg = 0; eg < TE / 4; eg++) {
            float aA0 = 0.f, aA1 = 0.f, aA2 = 0.f, aA3 = 0.f;
            float aB0 = 0.f, aB1 = 0.f, aB2 = 0.f, aB3 = 0.f;
            #pragma unroll
            for (int k = 0; k < 32; k++) {
                float4 ha = *(const float4*)&hA[k * 68 + eg * 4];
                float4 hb = *(const float4*)&hB[k * 68 + eg * 4];
                aA0 += wf[k] * ha.x; aA1 += wf[k] * ha.y; aA2 += wf[k] * ha.z; aA3 += wf[k] * ha.w;
                aB0 += wl[k] * hb.x; aB1 += wl[k] * hb.y; aB2 += wl[k] * hb.z; aB3 += wl[k] * hb.w;
            }
            ws[(eg * 4 + 0) * 320 + c] = aA0 * aB0;
            ws[(eg * 4 + 1) * 320 + c] = aA1 * aB1;
            ws[(eg * 4 + 2) * 320 + c] = aA2 * aB2;
            ws[(eg * 4 + 3) * 320 + c] = aA3 * aB3;
        }
    }
    __syncthreads();
    // phase 2: tensor product + atomic scatter
    if (tid < 256) {
        const float PW_S = 0.44721359549995793f;    // sqrt(1/5)
        const float PW_V = 0.77459666924148337f;    // sqrt(3/5)
        const float IS3  = 0.57735026918962576f;    // 1/sqrt(3)
        const float IS2  = 0.70710678118654752f;    // 1/sqrt(2)
        int u = tid & 63, sub = tid >> 6;
        for (int e = sub; e < TE; e += 4) {
            int d = idxs[64 + e];
            if (d < 0) continue;
            int s = idxs[e];
            const float* xr = xg + s * 256;
            float es  = xr[u];
            float ev0 = xr[64 + u * 3], ev1 = xr[64 + u * 3 + 1], ev2 = xr[64 + u * 3 + 2];
            float s0 = shs[e * 4], s1 = shs[e * 4 + 1], s2 = shs[e * 4 + 2], s3 = shs[e * 4 + 3];
            const float* we = ws + e * 320;
            float w0 = we[u], w1 = we[64 + u], w2 = we[128 + u], w3 = we[192 + u], w4 = we[256 + u];
            float dotv = ev0 * s1 + ev1 * s2 + ev2 * s3;
            float c0 = ev1 * s3 - ev2 * s2;
            float c1 = ev2 * s1 - ev0 * s3;
            float c2 = ev0 * s2 - ev1 * s1;
            float outs = PW_S * (w0 * es * s0 + w3 * dotv * IS3);
            float k2 = PW_V * w2 * s0;
            float k4 = PW_V * w4 * IS2;
            float k1 = PW_V * w1 * es;
            float o0 = k1 * s1 + k2 * ev0 + k4 * c0;
            float o1 = k1 * s2 + k2 * ev1 + k4 * c1;
            float o2 = k1 * s3 + k2 * ev2 + k4 * c2;
            float* pa = acc + d * 256;
            atomicAdd(pa + u, outs);
            atomicAdd(pa + 64 + u * 3 + 0, o0);
            atomicAdd(pa + 64 + u * 3 + 1, o1);
            atomicAdd(pa + 64 + u * 3 + 2, o2);
        }
    }
}

// ---------------- launch ----------------------------------------------------
extern "C" void kernel_launch(void* const* d_in, const int* in_sizes, int n_in,
                              void* d_out, int out_size) {
    const float* x     = (const float*)d_in[0];
    const int*   ei    = (const int*)  d_in[1];
    const float* sh    = (const float*)d_in[2];
    const float* attr  = (const float*)d_in[3];
    const float* Wpre0 = (const float*)d_in[4];
    const float* bpre0 = (const float*)d_in[5];
    const float* Wpre1 = (const float*)d_in[6];
    const float* Wg1   = (const float*)d_in[7];
    const float* bg1   = (const float*)d_in[8];
    const float* Wg2   = (const float*)d_in[9];
    const float* bg2   = (const float*)d_in[10];
    const float* Wn0   = (const float*)d_in[11];
    const float* bn0   = (const float*)d_in[12];
    const float* Wn1   = (const float*)d_in[13];
    const float* Wf1   = (const float*)d_in[14];
    const float* Wf2   = (const float*)d_in[15];
    const float* Wl1   = (const float*)d_in[16];
    const float* Wl2   = (const float*)d_in[17];
    const float* Wo0   = (const float*)d_in[18];
    const float* bo0   = (const float*)d_in[19];
    const float* Wo1   = (const float*)d_in[20];

    int N = in_sizes[0] / 256;
    int E = in_sizes[1] / 2;

    float *pre, *tmp, *xgp, *accp, *h1a, *h1l;
    cudaGetSymbolAddress((void**)&pre,  g_pre);
    cudaGetSymbolAddress((void**)&tmp,  g_tmp);
    cudaGetSymbolAddress((void**)&xgp,  g_xg);
    cudaGetSymbolAddress((void**)&accp, g_acc);
    cudaGetSymbolAddress((void**)&h1a,  g_h1a);
    cudaGetSymbolAddress((void**)&h1l,  g_h1l);

    static const int GATE_SMEM = 34816 * 4;
    static const int EDGE_SMEM = (2 * 32 * 68 + 64 * 320 + 256 + 128) * 4;
    cudaFuncSetAttribute(gate_kernel, cudaFuncAttributeMaxDynamicSharedMemorySize, GATE_SMEM);
    cudaFuncSetAttribute(edge_kernel, cudaFuncAttributeMaxDynamicSharedMemorySize, EDGE_SMEM);

    prep_kernel<<<(320 * 32 + 255) / 256, 256>>>(Wf2, Wl2, Wl1);
    e3_kernel<<<(N + 3) / 4, 256>>>(x, Wpre0, bpre0, Wpre1, pre, nullptr, N);
    gate_kernel<<<(N + 7) / 8, 256, GATE_SMEM>>>(x, Wg1, bg1, Wg2, bg2, tmp, N);
    e3_kernel<<<(N + 3) / 4, 256>>>(tmp, Wn0, bn0, Wn1, xgp, accp, N);
    h1a_kernel<<<(E + 63) / 64, 256>>>(attr, Wf1, h1a, E);
    h1l_kernel<<<(E + 31) / 32, 256>>>(ei, pre, h1l, E, E);
    edge_kernel<<<(E + TE - 1) / TE, 320, EDGE_SMEM>>>(ei, sh, h1a, h1l, xgp, accp, E, E);
    e3_kernel<<<(N + 3) / 4, 256>>>(accp, Wo0, bo0, Wo1, (float*)d_out, nullptr, N);
}